// round 16
// baseline (speedup 1.0000x reference)
#include <cuda_runtime.h>
#include <math.h>
#include <stdint.h>

#define BB 16
#define CC 128
#define HH 64
#define WW 64
#define LL 4096
#define OO 128
#define HIDN 32
#define CGK 16
#define SEK 16
#define KKN 4
#define TAUF 1.5f
#define EPSF 1e-5f

// ---------------- device scratch (allowed: __device__ globals) ----------------
__device__ float d_p[BB*CC];
__device__ float d_g[BB*CC];
__device__ float d_m2[BB*CC];            // g * c_attn
__device__ float d_sinb[BB*2*LL];        // [b][2][L] mean/max over channels of x*g
__device__ float d_sattn[BB*LL];
__device__ float d_x2[(size_t)BB*CC*LL]; // fully gated input
__device__ float d_mean2[BB*CC];
__device__ float d_gf[BB*HIDN];
__device__ float d_lf[(size_t)BB*HIDN*LL];
__device__ float d_alpha[(size_t)BB*KKN*OO*LL];   // 128 MiB
__device__ float d_wT[5*CC*9*OO];        // [set][c][rs][o]
__device__ float d_psum[BB*OO*32];
__device__ float d_psumsq[BB*OO*32];
__device__ float d_Ag[BB*OO];
__device__ float d_Bg[BB*OO];

__device__ __forceinline__ float sigm(float x){ return 1.0f/(1.0f+__expf(-x)); }
__device__ __forceinline__ float siluf(float x){ return x*sigm(x); }

// ---------------- K1: per-(b,c) spatial mean of x ----------------
__global__ void kmean(const float* __restrict__ x){
    int bc = blockIdx.x; int t = threadIdx.x;
    const float* row = x + (size_t)bc*LL;
    float s = 0.f;
    for (int i = t; i < LL; i += 256) s += row[i];
    __shared__ float sm[256];
    sm[t] = s; __syncthreads();
    for (int off = 128; off > 0; off >>= 1){
        if (t < off) sm[t] += sm[t+off];
        __syncthreads();
    }
    if (t == 0) d_p[bc] = sm[0] / (float)LL;
}

// ---------------- K2: global-context gate + channel gate ----------------
__global__ void kgates(const float* __restrict__ gc_w1, const float* __restrict__ gc_w2,
                       const float* __restrict__ cg_w1, const float* __restrict__ cg_b1,
                       const float* __restrict__ cg_w2, const float* __restrict__ cg_b2){
    int b = blockIdx.x; int t = threadIdx.x;   // 128 threads; t == channel index
    __shared__ float ps[CC], hs[HIDN], pcs[CC], h2[CGK];
    ps[t] = d_p[b*CC + t];
    __syncthreads();
    if (t < HIDN){
        float a = 0.f;
        for (int c = 0; c < CC; c++) a += ps[c]*gc_w1[t*CC + c];
        hs[t] = siluf(a);
    }
    __syncthreads();
    float a = 0.f;
    for (int h = 0; h < HIDN; h++) a += hs[h]*gc_w2[t*HIDN + h];
    float g = sigm(a);
    d_g[b*CC + t] = g;
    pcs[t] = ps[t]*g;
    __syncthreads();
    if (t < CGK){
        float a2 = cg_b1[t];
        for (int c = 0; c < CC; c++) a2 += pcs[c]*cg_w1[t*CC + c];
        h2[t] = siluf(a2);
    }
    __syncthreads();
    float a3 = cg_b2[t];
    for (int i = 0; i < CGK; i++) a3 += h2[i]*cg_w2[t*CGK + i];
    d_m2[b*CC + t] = g*sigm(a3);
}

// ---------------- K3: channel mean/max of x*g per pixel ----------------
__global__ void kspatial(const float* __restrict__ x){
    int b = blockIdx.x / (LL/256);
    int l = (blockIdx.x % (LL/256))*256 + threadIdx.x;
    __shared__ float gs[CC];
    if (threadIdx.x < CC) gs[threadIdx.x] = d_g[b*CC + threadIdx.x];
    __syncthreads();
    const float* xb = x + (size_t)b*CC*LL + l;
    float mn = 0.f, mx = -1e30f;
    #pragma unroll 4
    for (int c = 0; c < CC; c++){
        float v = xb[(size_t)c*LL]*gs[c];
        mn += v; mx = fmaxf(mx, v);
    }
    d_sinb[(size_t)b*2*LL + l]       = mn / (float)CC;
    d_sinb[(size_t)b*2*LL + LL + l]  = mx;
}

// ---------------- K4: 7x7 spatial gate conv ----------------
__global__ void ksg(const float* __restrict__ sg_w){
    __shared__ float w[98];
    if (threadIdx.x < 98) w[threadIdx.x] = sg_w[threadIdx.x];
    __syncthreads();
    int b = blockIdx.x / (LL/256);
    int l = (blockIdx.x % (LL/256))*256 + threadIdx.x;
    int y = l >> 6, xx = l & 63;
    float acc = 0.f;
    for (int ch = 0; ch < 2; ch++){
        const float* sp = d_sinb + (size_t)b*2*LL + (size_t)ch*LL;
        for (int i = 0; i < 7; i++){
            int yy = y + i - 3; if (yy < 0 || yy >= HH) continue;
            for (int j = 0; j < 7; j++){
                int xj = xx + j - 3; if (xj < 0 || xj >= WW) continue;
                acc += sp[yy*WW + xj]*w[ch*49 + i*7 + j];
            }
        }
    }
    d_sattn[(size_t)b*LL + l] = sigm(acc);
}

// ---------------- K5: apply full gating -> x2, and its spatial mean ----------------
__global__ void kapply(const float* __restrict__ x){
    int bc = blockIdx.x; int b = bc / CC; int t = threadIdx.x;
    float m = d_m2[bc];
    const float* xr = x + (size_t)bc*LL;
    const float* sa = d_sattn + (size_t)b*LL;
    float* o = d_x2 + (size_t)bc*LL;
    float s = 0.f;
    for (int i = t; i < LL; i += 256){
        float v = xr[i]*m*sa[i];
        o[i] = v; s += v;
    }
    __shared__ float sm[256];
    sm[t] = s; __syncthreads();
    for (int off = 128; off > 0; off >>= 1){
        if (t < off) sm[t] += sm[t+off];
        __syncthreads();
    }
    if (t == 0) d_mean2[bc] = sm[0] / (float)LL;
}

// ---------------- K6: router global branch gf ----------------
__global__ void kgf(const float* __restrict__ rg_w){
    int b = blockIdx.x, h = threadIdx.x;   // 32 threads
    float a = 0.f;
    for (int c = 0; c < CC; c++) a += d_mean2[b*CC + c]*rg_w[h*CC + c];
    d_gf[b*HIDN + h] = siluf(a);
}

// ---------------- K7: transpose weights -> wT[set][c][rs][o] (with kernel_scale) ----------------
__global__ void kwT(const float* __restrict__ basew, const float* __restrict__ deltaw,
                    const float* __restrict__ kscale){
    int idx = blockIdx.x*256 + threadIdx.x;            // over 5*O*C*9
    if (idx >= 5*OO*CC*9) return;
    int s  = idx / (OO*CC*9);
    int r  = idx % (OO*CC*9);
    int o  = r / (CC*9);
    int cr = r % (CC*9);                               // c*9 + rs
    float w;
    if (s == 0) w = basew[(size_t)o*CC*9 + cr];
    else        w = deltaw[(size_t)(s-1)*OO*CC*9 + (size_t)o*CC*9 + cr]*kscale[(s-1)*OO + o];
    int c = cr / 9, rs = cr % 9;
    d_wT[((s*CC + c)*9 + rs)*OO + o] = w;
}

// ---------------- K8: router dilated conv + BN + SiLU + gf ----------------
__global__ void krconv(const float* __restrict__ rc_w,
                       const float* __restrict__ bn_gamma, const float* __restrict__ bn_beta,
                       const float* __restrict__ bn_mean,  const float* __restrict__ bn_var){
    int tile = blockIdx.x;         // 16 tiles of 16x16
    int b    = blockIdx.y;
    int ty0 = (tile >> 2)*16, tx0 = (tile & 3)*16;
    int t = threadIdx.x; int ty = t >> 4, tx = t & 15;
    __shared__ float patch[16][20][20];
    __shared__ float wsm[16][9][32];
    float acc[32];
    #pragma unroll
    for (int h = 0; h < 32; h++) acc[h] = 0.f;

    for (int cc = 0; cc < CC; cc += 16){
        __syncthreads();
        for (int idx = t; idx < 16*400; idx += 256){
            int c = idx / 400, rem = idx % 400, py = rem / 20, px = rem % 20;
            int gy = ty0 - 2 + py, gx = tx0 - 2 + px;
            float v = 0.f;
            if (gy >= 0 && gy < HH && gx >= 0 && gx < WW)
                v = d_x2[((size_t)(b*CC + cc + c))*LL + (gy << 6) + gx];
            patch[c][py][px] = v;
        }
        for (int idx = t; idx < 16*9*32; idx += 256){
            int c = idx / 288, rs = (idx % 288)/32, h = idx % 32;
            wsm[c][rs][h] = rc_w[((size_t)h*CC + cc + c)*9 + rs];
        }
        __syncthreads();
        for (int c = 0; c < 16; c++){
            float xv[9];
            #pragma unroll
            for (int r = 0; r < 3; r++)
                #pragma unroll
                for (int s = 0; s < 3; s++)
                    xv[r*3 + s] = patch[c][ty + 2*r][tx + 2*s];
            #pragma unroll
            for (int rs = 0; rs < 9; rs++){
                #pragma unroll
                for (int h4 = 0; h4 < 8; h4++){
                    float4 w = *(const float4*)&wsm[c][rs][h4*4];
                    acc[h4*4+0] += w.x*xv[rs];
                    acc[h4*4+1] += w.y*xv[rs];
                    acc[h4*4+2] += w.z*xv[rs];
                    acc[h4*4+3] += w.w*xv[rs];
                }
            }
        }
    }
    int l = (ty0 + ty)*WW + tx0 + tx;
    #pragma unroll
    for (int h = 0; h < 32; h++){
        float rinv = rsqrtf(bn_var[h] + EPSF);
        float v = (acc[h] - bn_mean[h])*rinv*bn_gamma[h] + bn_beta[h];
        v = siluf(v) + d_gf[b*HIDN + h];
        d_lf[((size_t)(b*HIDN + h))*LL + l] = v;
    }
}

// ---------------- K9: alpha = softmax_k((gate_w@lf + b)/TAU) ----------------
__global__ void kalpha(const float* __restrict__ gate_w, const float* __restrict__ gate_b){
    int ob = blockIdx.y*64;
    __shared__ float wsm[4*64*32];
    __shared__ float bsm[4*64];
    for (int idx = threadIdx.x; idx < 4*64*32; idx += 256){
        int k = idx/(64*32); int o = (idx/32) & 63; int h = idx & 31;
        wsm[idx] = gate_w[(k*128 + ob + o)*32 + h];
    }
    {
        int k = threadIdx.x/64, o = threadIdx.x & 63;
        bsm[threadIdx.x] = gate_b[k*128 + ob + o];
    }
    __syncthreads();
    int b  = blockIdx.x / (LL/512);
    int l0 = (blockIdx.x % (LL/512))*512 + threadIdx.x;
    int l1 = l0 + 256;
    float h0[32], h1[32];
    #pragma unroll
    for (int h = 0; h < 32; h++){
        h0[h] = d_lf[((size_t)(b*HIDN + h))*LL + l0];
        h1[h] = d_lf[((size_t)(b*HIDN + h))*LL + l1];
    }
    for (int o = 0; o < 64; o++){
        float z0[4], z1[4];
        #pragma unroll
        for (int k = 0; k < 4; k++){
            float a0 = 0.f, a1 = 0.f;
            const float* wrow = &wsm[(k*64 + o)*32];
            #pragma unroll
            for (int h = 0; h < 32; h++){
                float w = wrow[h];
                a0 += w*h0[h]; a1 += w*h1[h];
            }
            float bb = bsm[k*64 + o];
            z0[k] = a0 + bb; z1[k] = a1 + bb;
        }
        float m0 = fmaxf(fmaxf(z0[0],z0[1]),fmaxf(z0[2],z0[3]));
        float m1 = fmaxf(fmaxf(z1[0],z1[1]),fmaxf(z1[2],z1[3]));
        float e0[4], e1[4]; float s0 = 0.f, s1 = 0.f;
        #pragma unroll
        for (int k = 0; k < 4; k++){
            e0[k] = __expf((z0[k]-m0)*(1.0f/TAUF)); s0 += e0[k];
            e1[k] = __expf((z1[k]-m1)*(1.0f/TAUF)); s1 += e1[k];
        }
        float r0 = 1.f/s0, r1 = 1.f/s1;
        #pragma unroll
        for (int k = 0; k < 4; k++){
            size_t base = ((size_t)((b*4 + k)*128 + ob + o))*LL;
            d_alpha[base + l0] = e0[k]*r0;
            d_alpha[base + l1] = e1[k]*r1;
        }
    }
}

// ---------------- K10: main 5-way conv + alpha combine + GN partials ----------------
__global__ void __launch_bounds__(256,2)
kmain(float* __restrict__ out){
    int tile  = blockIdx.x;           // 0..31 : 4x in x (16 wide), 8x in y (8 tall)
    int ohalf = blockIdx.y;           // 0..1
    int b     = blockIdx.z;
    int ty0 = (tile >> 2)*8, tx0 = (tile & 3)*16;
    int t = threadIdx.x;
    int to = t & 7, tp = t >> 3;      // to: o-group, tp: pixel-group (0..31)
    int pr = tp >> 2, pc0 = (tp & 3)*4;

    __shared__ float patch[8][10][18];
    __shared__ float wsm[8][9][64];
    __shared__ float ssum[64], ssq[64];

    float outa[32];
    #pragma unroll
    for (int i = 0; i < 32; i++) outa[i] = 0.f;

    for (int set = 0; set < 5; set++){
        float acc[32];
        #pragma unroll
        for (int i = 0; i < 32; i++) acc[i] = 0.f;

        for (int cc = 0; cc < CC; cc += 8){
            __syncthreads();
            for (int idx = t; idx < 8*180; idx += 256){
                int c = idx/180, rem = idx%180, py = rem/18, px = rem%18;
                int gy = ty0 - 1 + py, gx = tx0 - 1 + px;
                float v = 0.f;
                if (gy >= 0 && gy < HH && gx >= 0 && gx < WW)
                    v = d_x2[((size_t)(b*CC + cc + c))*LL + (gy << 6) + gx];
                patch[c][py][px] = v;
            }
            const float* wbase = d_wT + ((size_t)(set*CC + cc)*9)*OO + ohalf*64;
            for (int idx = t; idx < 8*9*64; idx += 256){
                int c = idx/576, rs = (idx % 576)/64, o = idx & 63;
                wsm[c][rs][o] = wbase[(size_t)(c*9 + rs)*OO + o];
            }
            __syncthreads();

            for (int c = 0; c < 8; c++){
                #pragma unroll
                for (int r = 0; r < 3; r++){
                    float xv[6];
                    #pragma unroll
                    for (int j = 0; j < 6; j++) xv[j] = patch[c][pr + r][pc0 + j];
                    #pragma unroll
                    for (int s = 0; s < 3; s++){
                        float4 wa = *(const float4*)&wsm[c][r*3+s][to*8];
                        float4 wb = *(const float4*)&wsm[c][r*3+s][to*8 + 4];
                        float w8[8] = {wa.x,wa.y,wa.z,wa.w, wb.x,wb.y,wb.z,wb.w};
                        #pragma unroll
                        for (int oi = 0; oi < 8; oi++)
                            #pragma unroll
                            for (int pj = 0; pj < 4; pj++)
                                acc[oi*4 + pj] += w8[oi]*xv[s + pj];
                    }
                }
            }
        }
        // fold into output with alpha (set 0 = static, weight 1)
        if (set == 0){
            #pragma unroll
            for (int i = 0; i < 32; i++) outa[i] = acc[i];
        } else {
            int gy = ty0 + pr, gxb = tx0 + pc0;
            #pragma unroll
            for (int oi = 0; oi < 8; oi++){
                int o = ohalf*64 + to*8 + oi;
                const float* ap = d_alpha + ((size_t)((b*4 + (set-1))*128 + o))*LL + (gy << 6) + gxb;
                float4 av = *(const float4*)ap;
                outa[oi*4+0] += av.x*acc[oi*4+0];
                outa[oi*4+1] += av.y*acc[oi*4+1];
                outa[oi*4+2] += av.z*acc[oi*4+2];
                outa[oi*4+3] += av.w*acc[oi*4+3];
            }
        }
    }

    if (t < 64){ ssum[t] = 0.f; ssq[t] = 0.f; }
    __syncthreads();
    int gy = ty0 + pr, gxb = tx0 + pc0;
    #pragma unroll
    for (int oi = 0; oi < 8; oi++){
        int o = ohalf*64 + to*8 + oi;
        float4 v;
        v.x = outa[oi*4+0]; v.y = outa[oi*4+1]; v.z = outa[oi*4+2]; v.w = outa[oi*4+3];
        *(float4*)&out[((size_t)(b*OO + o))*LL + (gy << 6) + gxb] = v;
        float s = v.x + v.y + v.z + v.w;
        float q = v.x*v.x + v.y*v.y + v.z*v.z + v.w*v.w;
        atomicAdd(&ssum[to*8 + oi], s);
        atomicAdd(&ssq[to*8 + oi], q);
    }
    __syncthreads();
    if (t < 64){
        int o = ohalf*64 + t;
        d_psum  [(size_t)(b*OO + o)*32 + tile] = ssum[t];
        d_psumsq[(size_t)(b*OO + o)*32 + tile] = ssq[t];
    }
}

// ---------------- K11: GroupNorm stats + SE -> per-(b,o) affine ----------------
__global__ void kgn(const float* __restrict__ gn_gamma, const float* __restrict__ gn_beta,
                    const float* __restrict__ se_w1, const float* __restrict__ se_b1,
                    const float* __restrict__ se_w2, const float* __restrict__ se_b2,
                    const float* __restrict__ bias){
    int b = blockIdx.x, o = threadIdx.x;   // 128 threads
    float s = 0.f, q = 0.f;
    for (int i = 0; i < 32; i++){
        s += d_psum  [(size_t)(b*OO + o)*32 + i];
        q += d_psumsq[(size_t)(b*OO + o)*32 + i];
    }
    __shared__ float rs_[128], rq_[128], gs[8], gq[8], mnorm[128], h2[16];
    rs_[o] = s; rq_[o] = q;
    __syncthreads();
    if (o < 8){
        float a = 0.f, c = 0.f;
        for (int j = 0; j < 16; j++){ a += rs_[o*16 + j]; c += rq_[o*16 + j]; }
        gs[o] = a; gq[o] = c;
    }
    __syncthreads();
    float N = 16.f*4096.f;
    float mu  = gs[o >> 4]/N;
    float var = gq[o >> 4]/N - mu*mu;
    float rinv = rsqrtf(var + EPSF);
    float ga = gn_gamma[o], be = gn_beta[o];
    mnorm[o] = (s/(float)LL - mu)*rinv*ga + be;
    __syncthreads();
    if (o < 16){
        float a = se_b1[o];
        for (int j = 0; j < 128; j++) a += mnorm[j]*se_w1[o*128 + j];
        h2[o] = siluf(a);
    }
    __syncthreads();
    float a = se_b2[o];
    for (int i = 0; i < 16; i++) a += h2[i]*se_w2[o*16 + i];
    float se = sigm(a);
    d_Ag[b*OO + o] = rinv*ga*se;
    d_Bg[b*OO + o] = (be - mu*rinv*ga)*se + bias[o];
}

// ---------------- K12: final affine + residual + bias ----------------
__global__ void kfinal(const float* __restrict__ x, const float* __restrict__ iscale,
                       float* __restrict__ out){
    size_t i = ((size_t)blockIdx.x*256 + threadIdx.x)*4;
    int bo = (int)(i >> 12);
    float tis = tanhf(iscale[0]);
    float4 f  = *(float4*)&out[i];
    float4 xi = *(const float4*)&x[i];
    float A = d_Ag[bo], Bc = d_Bg[bo];
    f.x = f.x*A + Bc + tis*xi.x;
    f.y = f.y*A + Bc + tis*xi.y;
    f.z = f.z*A + Bc + tis*xi.z;
    f.w = f.w*A + Bc + tis*xi.w;
    *(float4*)&out[i] = f;
}

// ---------------- launcher ----------------
extern "C" void kernel_launch(void* const* d_in, const int* in_sizes, int n_in,
                              void* d_out, int out_size){
    const float* x            = (const float*)d_in[0];
    const float* base_weight  = (const float*)d_in[1];
    const float* delta_weight = (const float*)d_in[2];
    const float* kernel_scale = (const float*)d_in[3];
    const float* gc_w1        = (const float*)d_in[4];
    const float* gc_w2        = (const float*)d_in[5];
    const float* rc_w         = (const float*)d_in[6];
    const float* bn_gamma     = (const float*)d_in[7];
    const float* bn_beta      = (const float*)d_in[8];
    const float* bn_mean      = (const float*)d_in[9];
    const float* bn_var       = (const float*)d_in[10];
    const float* rg_w         = (const float*)d_in[11];
    const float* gate_w       = (const float*)d_in[12];
    const float* gate_b       = (const float*)d_in[13];
    const float* cg_w1        = (const float*)d_in[14];
    const float* cg_b1        = (const float*)d_in[15];
    const float* cg_w2        = (const float*)d_in[16];
    const float* cg_b2        = (const float*)d_in[17];
    const float* sg_w         = (const float*)d_in[18];
    const float* gn_gamma     = (const float*)d_in[19];
    const float* gn_beta      = (const float*)d_in[20];
    const float* se_w1        = (const float*)d_in[21];
    const float* se_b1        = (const float*)d_in[22];
    const float* se_w2        = (const float*)d_in[23];
    const float* se_b2        = (const float*)d_in[24];
    const float* iscale       = (const float*)d_in[25];
    const float* bias         = (const float*)d_in[26];
    float* out = (float*)d_out;

    kmean  <<<BB*CC, 256>>>(x);
    kgates <<<BB, 128>>>(gc_w1, gc_w2, cg_w1, cg_b1, cg_w2, cg_b2);
    kspatial<<<BB*(LL/256), 256>>>(x);
    ksg    <<<BB*(LL/256), 256>>>(sg_w);
    kapply <<<BB*CC, 256>>>(x);
    kgf    <<<BB, 32>>>(rg_w);
    kwT    <<<(5*OO*CC*9)/256, 256>>>(base_weight, delta_weight, kernel_scale);
    krconv <<<dim3(16, BB), 256>>>(rc_w, bn_gamma, bn_beta, bn_mean, bn_var);
    kalpha <<<dim3(BB*(LL/512), 2), 256>>>(gate_w, gate_b);
    kmain  <<<dim3(32, 2, BB), 256>>>(out);
    kgn    <<<BB, 128>>>(gn_gamma, gn_beta, se_w1, se_b1, se_w2, se_b2, bias);
    kfinal <<<(BB*OO*LL)/(256*4), 256>>>(x, iscale, out);
}

// round 17
// speedup vs baseline: 1.5999x; 1.5999x over previous
#include <cuda_runtime.h>
#include <math.h>
#include <stdint.h>

#define BB 16
#define CC 128
#define HH 64
#define WW 64
#define LL 4096
#define OO 128
#define HIDN 32
#define CGK 16
#define SEK 16
#define KKN 4
#define TAUF 1.5f
#define EPSF 1e-5f

// ---------------- device scratch (allowed: __device__ globals) ----------------
__device__ float d_p[BB*CC];
__device__ float d_g[BB*CC];
__device__ float d_m2[BB*CC];            // g * c_attn
__device__ float d_sinb[BB*2*LL];        // [b][2][L] mean/max over channels of x*g
__device__ float d_sattn[BB*LL];
__device__ float d_x2[(size_t)BB*CC*LL]; // fully gated input
__device__ float d_mean2[BB*CC];
__device__ float d_gf[BB*HIDN];
__device__ float d_lf[(size_t)BB*HIDN*LL];
__device__ float d_alpha[(size_t)BB*KKN*OO*LL];   // 128 MiB
__device__ float d_wT[5*CC*9*OO];        // [set][c][rs][o]
__device__ float d_psum[BB*OO*32];
__device__ float d_psumsq[BB*OO*32];
__device__ float d_Ag[BB*OO];
__device__ float d_Bg[BB*OO];

__device__ __forceinline__ float sigm(float x){ return 1.0f/(1.0f+__expf(-x)); }
__device__ __forceinline__ float siluf(float x){ return x*sigm(x); }

// ---------------- K1: per-(b,c) spatial mean of x ----------------
__global__ void kmean(const float* __restrict__ x){
    int bc = blockIdx.x; int t = threadIdx.x;
    const float* row = x + (size_t)bc*LL;
    float s = 0.f;
    for (int i = t; i < LL; i += 256) s += row[i];
    __shared__ float sm[256];
    sm[t] = s; __syncthreads();
    for (int off = 128; off > 0; off >>= 1){
        if (t < off) sm[t] += sm[t+off];
        __syncthreads();
    }
    if (t == 0) d_p[bc] = sm[0] / (float)LL;
}

// ---------------- K2: global-context gate + channel gate ----------------
__global__ void kgates(const float* __restrict__ gc_w1, const float* __restrict__ gc_w2,
                       const float* __restrict__ cg_w1, const float* __restrict__ cg_b1,
                       const float* __restrict__ cg_w2, const float* __restrict__ cg_b2){
    int b = blockIdx.x; int t = threadIdx.x;   // 128 threads; t == channel index
    __shared__ float ps[CC], hs[HIDN], pcs[CC], h2[CGK];
    ps[t] = d_p[b*CC + t];
    __syncthreads();
    if (t < HIDN){
        float a = 0.f;
        for (int c = 0; c < CC; c++) a += ps[c]*gc_w1[t*CC + c];
        hs[t] = siluf(a);
    }
    __syncthreads();
    float a = 0.f;
    for (int h = 0; h < HIDN; h++) a += hs[h]*gc_w2[t*HIDN + h];
    float g = sigm(a);
    d_g[b*CC + t] = g;
    pcs[t] = ps[t]*g;
    __syncthreads();
    if (t < CGK){
        float a2 = cg_b1[t];
        for (int c = 0; c < CC; c++) a2 += pcs[c]*cg_w1[t*CC + c];
        h2[t] = siluf(a2);
    }
    __syncthreads();
    float a3 = cg_b2[t];
    for (int i = 0; i < CGK; i++) a3 += h2[i]*cg_w2[t*CGK + i];
    d_m2[b*CC + t] = g*sigm(a3);
}

// ---------------- K3: channel mean/max of x*g per pixel ----------------
__global__ void kspatial(const float* __restrict__ x){
    int b = blockIdx.x / (LL/256);
    int l = (blockIdx.x % (LL/256))*256 + threadIdx.x;
    __shared__ float gs[CC];
    if (threadIdx.x < CC) gs[threadIdx.x] = d_g[b*CC + threadIdx.x];
    __syncthreads();
    const float* xb = x + (size_t)b*CC*LL + l;
    float mn = 0.f, mx = -1e30f;
    #pragma unroll 4
    for (int c = 0; c < CC; c++){
        float v = xb[(size_t)c*LL]*gs[c];
        mn += v; mx = fmaxf(mx, v);
    }
    d_sinb[(size_t)b*2*LL + l]       = mn / (float)CC;
    d_sinb[(size_t)b*2*LL + LL + l]  = mx;
}

// ---------------- K4: 7x7 spatial gate conv ----------------
__global__ void ksg(const float* __restrict__ sg_w){
    __shared__ float w[98];
    if (threadIdx.x < 98) w[threadIdx.x] = sg_w[threadIdx.x];
    __syncthreads();
    int b = blockIdx.x / (LL/256);
    int l = (blockIdx.x % (LL/256))*256 + threadIdx.x;
    int y = l >> 6, xx = l & 63;
    float acc = 0.f;
    for (int ch = 0; ch < 2; ch++){
        const float* sp = d_sinb + (size_t)b*2*LL + (size_t)ch*LL;
        for (int i = 0; i < 7; i++){
            int yy = y + i - 3; if (yy < 0 || yy >= HH) continue;
            for (int j = 0; j < 7; j++){
                int xj = xx + j - 3; if (xj < 0 || xj >= WW) continue;
                acc += sp[yy*WW + xj]*w[ch*49 + i*7 + j];
            }
        }
    }
    d_sattn[(size_t)b*LL + l] = sigm(acc);
}

// ---------------- K5: apply full gating -> x2, and its spatial mean ----------------
__global__ void kapply(const float* __restrict__ x){
    int bc = blockIdx.x; int b = bc / CC; int t = threadIdx.x;
    float m = d_m2[bc];
    const float* xr = x + (size_t)bc*LL;
    const float* sa = d_sattn + (size_t)b*LL;
    float* o = d_x2 + (size_t)bc*LL;
    float s = 0.f;
    for (int i = t; i < LL; i += 256){
        float v = xr[i]*m*sa[i];
        o[i] = v; s += v;
    }
    __shared__ float sm[256];
    sm[t] = s; __syncthreads();
    for (int off = 128; off > 0; off >>= 1){
        if (t < off) sm[t] += sm[t+off];
        __syncthreads();
    }
    if (t == 0) d_mean2[bc] = sm[0] / (float)LL;
}

// ---------------- K6: router global branch gf ----------------
__global__ void kgf(const float* __restrict__ rg_w){
    int b = blockIdx.x, h = threadIdx.x;   // 32 threads
    float a = 0.f;
    for (int c = 0; c < CC; c++) a += d_mean2[b*CC + c]*rg_w[h*CC + c];
    d_gf[b*HIDN + h] = siluf(a);
}

// ---------------- K7: transpose weights -> wT[set][c][rs][o] (with kernel_scale) ----------------
__global__ void kwT(const float* __restrict__ basew, const float* __restrict__ deltaw,
                    const float* __restrict__ kscale){
    int idx = blockIdx.x*256 + threadIdx.x;            // over 5*O*C*9
    if (idx >= 5*OO*CC*9) return;
    int s  = idx / (OO*CC*9);
    int r  = idx % (OO*CC*9);
    int o  = r / (CC*9);
    int cr = r % (CC*9);                               // c*9 + rs
    float w;
    if (s == 0) w = basew[(size_t)o*CC*9 + cr];
    else        w = deltaw[(size_t)(s-1)*OO*CC*9 + (size_t)o*CC*9 + cr]*kscale[(s-1)*OO + o];
    int c = cr / 9, rs = cr % 9;
    d_wT[((s*CC + c)*9 + rs)*OO + o] = w;
}

// ---------------- K8: router dilated conv + BN + SiLU + gf ----------------
__global__ void krconv(const float* __restrict__ rc_w,
                       const float* __restrict__ bn_gamma, const float* __restrict__ bn_beta,
                       const float* __restrict__ bn_mean,  const float* __restrict__ bn_var){
    int tile = blockIdx.x;         // 16 tiles of 16x16
    int b    = blockIdx.y;
    int ty0 = (tile >> 2)*16, tx0 = (tile & 3)*16;
    int t = threadIdx.x; int ty = t >> 4, tx = t & 15;
    __shared__ float patch[16][20][20];
    __shared__ float wsm[16][9][32];
    float acc[32];
    #pragma unroll
    for (int h = 0; h < 32; h++) acc[h] = 0.f;

    for (int cc = 0; cc < CC; cc += 16){
        __syncthreads();
        for (int idx = t; idx < 16*400; idx += 256){
            int c = idx / 400, rem = idx % 400, py = rem / 20, px = rem % 20;
            int gy = ty0 - 2 + py, gx = tx0 - 2 + px;
            float v = 0.f;
            if (gy >= 0 && gy < HH && gx >= 0 && gx < WW)
                v = d_x2[((size_t)(b*CC + cc + c))*LL + (gy << 6) + gx];
            patch[c][py][px] = v;
        }
        for (int idx = t; idx < 16*9*32; idx += 256){
            int c = idx / 288, rs = (idx % 288)/32, h = idx % 32;
            wsm[c][rs][h] = rc_w[((size_t)h*CC + cc + c)*9 + rs];
        }
        __syncthreads();
        for (int c = 0; c < 16; c++){
            float xv[9];
            #pragma unroll
            for (int r = 0; r < 3; r++)
                #pragma unroll
                for (int s = 0; s < 3; s++)
                    xv[r*3 + s] = patch[c][ty + 2*r][tx + 2*s];
            #pragma unroll
            for (int rs = 0; rs < 9; rs++){
                #pragma unroll
                for (int h4 = 0; h4 < 8; h4++){
                    float4 w = *(const float4*)&wsm[c][rs][h4*4];
                    acc[h4*4+0] += w.x*xv[rs];
                    acc[h4*4+1] += w.y*xv[rs];
                    acc[h4*4+2] += w.z*xv[rs];
                    acc[h4*4+3] += w.w*xv[rs];
                }
            }
        }
    }
    int l = (ty0 + ty)*WW + tx0 + tx;
    #pragma unroll
    for (int h = 0; h < 32; h++){
        float rinv = rsqrtf(bn_var[h] + EPSF);
        float v = (acc[h] - bn_mean[h])*rinv*bn_gamma[h] + bn_beta[h];
        v = siluf(v) + d_gf[b*HIDN + h];
        d_lf[((size_t)(b*HIDN + h))*LL + l] = v;
    }
}

// ---------------- K9: alpha = softmax_k((gate_w@lf + b)/TAU) ----------------
__global__ void kalpha(const float* __restrict__ gate_w, const float* __restrict__ gate_b){
    int ob = blockIdx.y*64;
    __shared__ float wsm[4*64*32];
    __shared__ float bsm[4*64];
    for (int idx = threadIdx.x; idx < 4*64*32; idx += 256){
        int k = idx/(64*32); int o = (idx/32) & 63; int h = idx & 31;
        wsm[idx] = gate_w[(k*128 + ob + o)*32 + h];
    }
    {
        int k = threadIdx.x/64, o = threadIdx.x & 63;
        bsm[threadIdx.x] = gate_b[k*128 + ob + o];
    }
    __syncthreads();
    int b  = blockIdx.x / (LL/512);
    int l0 = (blockIdx.x % (LL/512))*512 + threadIdx.x;
    int l1 = l0 + 256;
    float h0[32], h1[32];
    #pragma unroll
    for (int h = 0; h < 32; h++){
        h0[h] = d_lf[((size_t)(b*HIDN + h))*LL + l0];
        h1[h] = d_lf[((size_t)(b*HIDN + h))*LL + l1];
    }
    for (int o = 0; o < 64; o++){
        float z0[4], z1[4];
        #pragma unroll
        for (int k = 0; k < 4; k++){
            float a0 = 0.f, a1 = 0.f;
            const float* wrow = &wsm[(k*64 + o)*32];
            #pragma unroll
            for (int h = 0; h < 32; h++){
                float w = wrow[h];
                a0 += w*h0[h]; a1 += w*h1[h];
            }
            float bb = bsm[k*64 + o];
            z0[k] = a0 + bb; z1[k] = a1 + bb;
        }
        float m0 = fmaxf(fmaxf(z0[0],z0[1]),fmaxf(z0[2],z0[3]));
        float m1 = fmaxf(fmaxf(z1[0],z1[1]),fmaxf(z1[2],z1[3]));
        float e0[4], e1[4]; float s0 = 0.f, s1 = 0.f;
        #pragma unroll
        for (int k = 0; k < 4; k++){
            e0[k] = __expf((z0[k]-m0)*(1.0f/TAUF)); s0 += e0[k];
            e1[k] = __expf((z1[k]-m1)*(1.0f/TAUF)); s1 += e1[k];
        }
        float r0 = 1.f/s0, r1 = 1.f/s1;
        #pragma unroll
        for (int k = 0; k < 4; k++){
            size_t base = ((size_t)((b*4 + k)*128 + ob + o))*LL;
            d_alpha[base + l0] = e0[k]*r0;
            d_alpha[base + l1] = e1[k]*r1;
        }
    }
}

// ---------------- K10: main 5-way conv + alpha combine + GN partials ----------------
__global__ void __launch_bounds__(256,2)
kmain(float* __restrict__ out){
    int tile  = blockIdx.x;           // 0..31 : 4x in x (16 wide), 8x in y (8 tall)
    int ohalf = blockIdx.y;           // 0..1
    int b     = blockIdx.z;
    int ty0 = (tile >> 2)*8, tx0 = (tile & 3)*16;
    int t = threadIdx.x;
    int to = t & 7, tp = t >> 3;      // to: o-group, tp: pixel-group (0..31)
    int pr = tp >> 2, pc0 = (tp & 3)*4;

    __shared__ float patch[8][10][18];
    __shared__ float wsm[8][9][64];
    __shared__ float ssum[64], ssq[64];

    float outa[32];
    #pragma unroll
    for (int i = 0; i < 32; i++) outa[i] = 0.f;

    for (int set = 0; set < 5; set++){
        float acc[32];
        #pragma unroll
        for (int i = 0; i < 32; i++) acc[i] = 0.f;

        for (int cc = 0; cc < CC; cc += 8){
            __syncthreads();
            for (int idx = t; idx < 8*180; idx += 256){
                int c = idx/180, rem = idx%180, py = rem/18, px = rem%18;
                int gy = ty0 - 1 + py, gx = tx0 - 1 + px;
                float v = 0.f;
                if (gy >= 0 && gy < HH && gx >= 0 && gx < WW)
                    v = d_x2[((size_t)(b*CC + cc + c))*LL + (gy << 6) + gx];
                patch[c][py][px] = v;
            }
            const float* wbase = d_wT + ((size_t)(set*CC + cc)*9)*OO + ohalf*64;
            for (int idx = t; idx < 8*9*64; idx += 256){
                int c = idx/576, rs = (idx % 576)/64, o = idx & 63;
                wsm[c][rs][o] = wbase[(size_t)(c*9 + rs)*OO + o];
            }
            __syncthreads();

            for (int c = 0; c < 8; c++){
                #pragma unroll
                for (int r = 0; r < 3; r++){
                    float xv[6];
                    #pragma unroll
                    for (int j = 0; j < 6; j++) xv[j] = patch[c][pr + r][pc0 + j];
                    #pragma unroll
                    for (int s = 0; s < 3; s++){
                        float4 wa = *(const float4*)&wsm[c][r*3+s][to*8];
                        float4 wb = *(const float4*)&wsm[c][r*3+s][to*8 + 4];
                        float w8[8] = {wa.x,wa.y,wa.z,wa.w, wb.x,wb.y,wb.z,wb.w};
                        #pragma unroll
                        for (int oi = 0; oi < 8; oi++)
                            #pragma unroll
                            for (int pj = 0; pj < 4; pj++)
                                acc[oi*4 + pj] += w8[oi]*xv[s + pj];
                    }
                }
            }
        }
        // fold into output with alpha (set 0 = static, weight 1)
        if (set == 0){
            #pragma unroll
            for (int i = 0; i < 32; i++) outa[i] = acc[i];
        } else {
            int gy = ty0 + pr, gxb = tx0 + pc0;
            #pragma unroll
            for (int oi = 0; oi < 8; oi++){
                int o = ohalf*64 + to*8 + oi;
                const float* ap = d_alpha + ((size_t)((b*4 + (set-1))*128 + o))*LL + (gy << 6) + gxb;
                float4 av = *(const float4*)ap;
                outa[oi*4+0] += av.x*acc[oi*4+0];
                outa[oi*4+1] += av.y*acc[oi*4+1];
                outa[oi*4+2] += av.z*acc[oi*4+2];
                outa[oi*4+3] += av.w*acc[oi*4+3];
            }
        }
    }

    if (t < 64){ ssum[t] = 0.f; ssq[t] = 0.f; }
    __syncthreads();
    int gy = ty0 + pr, gxb = tx0 + pc0;
    #pragma unroll
    for (int oi = 0; oi < 8; oi++){
        int o = ohalf*64 + to*8 + oi;
        float4 v;
        v.x = outa[oi*4+0]; v.y = outa[oi*4+1]; v.z = outa[oi*4+2]; v.w = outa[oi*4+3];
        *(float4*)&out[((size_t)(b*OO + o))*LL + (gy << 6) + gxb] = v;
        float s = v.x + v.y + v.z + v.w;
        float q = v.x*v.x + v.y*v.y + v.z*v.z + v.w*v.w;
        atomicAdd(&ssum[to*8 + oi], s);
        atomicAdd(&ssq[to*8 + oi], q);
    }
    __syncthreads();
    if (t < 64){
        int o = ohalf*64 + t;
        d_psum  [(size_t)(b*OO + o)*32 + tile] = ssum[t];
        d_psumsq[(size_t)(b*OO + o)*32 + tile] = ssq[t];
    }
}

// ---------------- K11: GroupNorm stats + SE -> per-(b,o) affine ----------------
__global__ void kgn(const float* __restrict__ gn_gamma, const float* __restrict__ gn_beta,
                    const float* __restrict__ se_w1, const float* __restrict__ se_b1,
                    const float* __restrict__ se_w2, const float* __restrict__ se_b2,
                    const float* __restrict__ bias){
    int b = blockIdx.x, o = threadIdx.x;   // 128 threads
    float s = 0.f, q = 0.f;
    for (int i = 0; i < 32; i++){
        s += d_psum  [(size_t)(b*OO + o)*32 + i];
        q += d_psumsq[(size_t)(b*OO + o)*32 + i];
    }
    __shared__ float rs_[128], rq_[128], gs[8], gq[8], mnorm[128], h2[16];
    rs_[o] = s; rq_[o] = q;
    __syncthreads();
    if (o < 8){
        float a = 0.f, c = 0.f;
        for (int j = 0; j < 16; j++){ a += rs_[o*16 + j]; c += rq_[o*16 + j]; }
        gs[o] = a; gq[o] = c;
    }
    __syncthreads();
    float N = 16.f*4096.f;
    float mu  = gs[o >> 4]/N;
    float var = gq[o >> 4]/N - mu*mu;
    float rinv = rsqrtf(var + EPSF);
    float ga = gn_gamma[o], be = gn_beta[o];
    mnorm[o] = (s/(float)LL - mu)*rinv*ga + be;
    __syncthreads();
    if (o < 16){
        float a = se_b1[o];
        for (int j = 0; j < 128; j++) a += mnorm[j]*se_w1[o*128 + j];
        h2[o] = siluf(a);
    }
    __syncthreads();
    float a = se_b2[o];
    for (int i = 0; i < 16; i++) a += h2[i]*se_w2[o*16 + i];
    float se = sigm(a);
    d_Ag[b*OO + o] = rinv*ga*se;
    d_Bg[b*OO + o] = (be - mu*rinv*ga)*se + bias[o];
}

// ---------------- K12: final affine + residual + bias ----------------
__global__ void kfinal(const float* __restrict__ x, const float* __restrict__ iscale,
                       float* __restrict__ out){
    size_t i = ((size_t)blockIdx.x*256 + threadIdx.x)*4;
    int bo = (int)(i >> 12);
    float tis = tanhf(iscale[0]);
    float4 f  = *(float4*)&out[i];
    float4 xi = *(const float4*)&x[i];
    float A = d_Ag[bo], Bc = d_Bg[bo];
    f.x = f.x*A + Bc + tis*xi.x;
    f.y = f.y*A + Bc + tis*xi.y;
    f.z = f.z*A + Bc + tis*xi.z;
    f.w = f.w*A + Bc + tis*xi.w;
    *(float4*)&out[i] = f;
}

// ---------------- launcher ----------------
extern "C" void kernel_launch(void* const* d_in, const int* in_sizes, int n_in,
                              void* d_out, int out_size){
    const float* x            = (const float*)d_in[0];
    const float* base_weight  = (const float*)d_in[1];
    const float* delta_weight = (const float*)d_in[2];
    const float* kernel_scale = (const float*)d_in[3];
    const float* gc_w1        = (const float*)d_in[4];
    const float* gc_w2        = (const float*)d_in[5];
    const float* rc_w         = (const float*)d_in[6];
    const float* bn_gamma     = (const float*)d_in[7];
    const float* bn_beta      = (const float*)d_in[8];
    const float* bn_mean      = (const float*)d_in[9];
    const float* bn_var       = (const float*)d_in[10];
    const float* rg_w         = (const float*)d_in[11];
    const float* gate_w       = (const float*)d_in[12];
    const float* gate_b       = (const float*)d_in[13];
    const float* cg_w1        = (const float*)d_in[14];
    const float* cg_b1        = (const float*)d_in[15];
    const float* cg_w2        = (const float*)d_in[16];
    const float* cg_b2        = (const float*)d_in[17];
    const float* sg_w         = (const float*)d_in[18];
    const float* gn_gamma     = (const float*)d_in[19];
    const float* gn_beta      = (const float*)d_in[20];
    const float* se_w1        = (const float*)d_in[21];
    const float* se_b1        = (const float*)d_in[22];
    const float* se_w2        = (const float*)d_in[23];
    const float* se_b2        = (const float*)d_in[24];
    const float* iscale       = (const float*)d_in[25];
    const float* bias         = (const float*)d_in[26];
    float* out = (float*)d_out;

    kmean  <<<BB*CC, 256>>>(x);
    kgates <<<BB, 128>>>(gc_w1, gc_w2, cg_w1, cg_b1, cg_w2, cg_b2);
    kspatial<<<BB*(LL/256), 256>>>(x);
    ksg    <<<BB*(LL/256), 256>>>(sg_w);
    kapply <<<BB*CC, 256>>>(x);
    kgf    <<<BB, 32>>>(rg_w);
    kwT    <<<(5*OO*CC*9)/256, 256>>>(base_weight, delta_weight, kernel_scale);
    krconv <<<dim3(16, BB), 256>>>(rc_w, bn_gamma, bn_beta, bn_mean, bn_var);
    kalpha <<<dim3(BB*(LL/512), 2), 256>>>(gate_w, gate_b);
    kmain  <<<dim3(32, 2, BB), 256>>>(out);
    kgn    <<<BB, 128>>>(gn_gamma, gn_beta, se_w1, se_b1, se_w2, se_b2, bias);
    kfinal <<<(BB*OO*LL)/(256*4), 256>>>(x, iscale, out);
}